// round 1
// baseline (speedup 1.0000x reference)
#include <cuda_runtime.h>
#include <stdint.h>

// SNU: out[b,h,t] = spike recurrence over xw[t,b,h] = sum_i x[b,i,t] * W[i,h]
// B=128, I=512, H=512, T=512.  DECAY=0.8
//
// Phase 1: fp32 SGEMM (M=B*T=65536, N=H=512, K=I=512) using packed fma.rn.f32x2
//          into scratch g_xw laid out [(b*T+t)][h]  (h contiguous).
// Phase 2: per-(b,h) sequential recurrence over t with SMEM transpose for
//          coalesced [b][h][t] output stores.

typedef unsigned long long ull;

__device__ float g_xw[33554432];   // 65536 x 512 floats = 134 MB scratch

// ---------------------------------------------------------------------------
// GEMM: C[m*512 + n] = sum_k X[b*262144 + k*512 + t] * W[k*512 + n]
// where m = b*512 + t.  Tiles: BM=BN=128, BK=8, 256 threads, 8x8 microtile.
// Accumulators packed as f32x2 pairs along N -> fma.rn.f32x2 (2 FMA/instr).
// ---------------------------------------------------------------------------
__global__ __launch_bounds__(256, 2) void gemm_kernel(
    const float* __restrict__ X, const float* __restrict__ W)
{
    __shared__ float As[2][8][128];
    __shared__ float Bs[2][8][128];

    const int bn = blockIdx.x * 128;          // N offset
    const int m0 = blockIdx.y * 128;          // M offset
    const int batch = m0 >> 9;                // T=512 divides tiles: one b per tile
    const int t0 = m0 & 511;

    const float* Xb = X + (size_t)batch * 262144 + t0;  // + k*512 + mm
    const float* Wb = W + bn;                            // + k*512 + nn

    const int tid = threadIdx.x;
    const int lk = tid >> 5;                  // 0..7   (k within tile)
    const int lv = (tid & 31) * 4;            // 0..124 (m or n, float4)

    const int tx = tid & 15;                  // n microtile
    const int ty = tid >> 4;                  // m microtile

    ull c2[8][4];
    #pragma unroll
    for (int i = 0; i < 8; i++)
        #pragma unroll
        for (int j = 0; j < 4; j++) c2[i][j] = 0ull;

    // preload tile 0
    float4 ra = *(const float4*)(Xb + lk * 512 + lv);
    float4 rb = *(const float4*)(Wb + lk * 512 + lv);
    *(float4*)&As[0][lk][lv] = ra;
    *(float4*)&Bs[0][lk][lv] = rb;
    __syncthreads();

    int buf = 0;
    #pragma unroll 1
    for (int k0 = 0; k0 < 512; k0 += 8) {
        const bool has_next = (k0 + 8) < 512;
        if (has_next) {
            ra = *(const float4*)(Xb + (size_t)(k0 + 8 + lk) * 512 + lv);
            rb = *(const float4*)(Wb + (size_t)(k0 + 8 + lk) * 512 + lv);
        }
        #pragma unroll
        for (int kk = 0; kk < 8; kk++) {
            float4 a0 = *(const float4*)&As[buf][kk][ty * 8];
            float4 a1 = *(const float4*)&As[buf][kk][ty * 8 + 4];
            const ull* bp = (const ull*)&Bs[buf][kk][tx * 8];
            ull b0 = bp[0], b1 = bp[1], b2v = bp[2], b3 = bp[3];
            float av[8] = {a0.x, a0.y, a0.z, a0.w, a1.x, a1.y, a1.z, a1.w};
            #pragma unroll
            for (int i = 0; i < 8; i++) {
                ull a2;
                asm("mov.b64 %0, {%1, %1};" : "=l"(a2) : "f"(av[i]));
                asm("fma.rn.f32x2 %0, %1, %2, %0;" : "+l"(c2[i][0]) : "l"(a2), "l"(b0));
                asm("fma.rn.f32x2 %0, %1, %2, %0;" : "+l"(c2[i][1]) : "l"(a2), "l"(b1));
                asm("fma.rn.f32x2 %0, %1, %2, %0;" : "+l"(c2[i][2]) : "l"(a2), "l"(b2v));
                asm("fma.rn.f32x2 %0, %1, %2, %0;" : "+l"(c2[i][3]) : "l"(a2), "l"(b3));
            }
        }
        if (has_next) {
            *(float4*)&As[buf ^ 1][lk][lv] = ra;
            *(float4*)&Bs[buf ^ 1][lk][lv] = rb;
            __syncthreads();
            buf ^= 1;
        }
    }

    // epilogue: packed pair == two consecutive fp32 -> store as 8B words
    #pragma unroll
    for (int i = 0; i < 8; i++) {
        ull* dst = (ull*)(g_xw + (size_t)(m0 + ty * 8 + i) * 512 + bn + tx * 8);
        #pragma unroll
        for (int j = 0; j < 4; j++) dst[j] = c2[i][j];
    }
}

// ---------------------------------------------------------------------------
// Recurrence: h = relu(xw_t + 0.8*h*(1-y));  y = (h + bias > 0)
// out[b][h][t] = y.  One thread per (b,h) lane; SMEM-staged transposed stores.
// ---------------------------------------------------------------------------
__global__ __launch_bounds__(128) void recur_kernel(
    const float* __restrict__ bias, float* __restrict__ out)
{
    const int b  = blockIdx.x >> 2;
    const int h0 = (blockIdx.x & 3) * 128;
    const int h  = h0 + threadIdx.x;

    const float bb = bias[h];
    float hs = 0.0f, y = 0.0f;

    const float* p  = g_xw + (size_t)b * 262144 + h;          // + t*512
    float*       po = out + ((size_t)b * 512 + h0) * 512;     // row base

    __shared__ float buf[128][33];

    for (int tc = 0; tc < 512; tc += 32) {
        #pragma unroll
        for (int j = 0; j < 32; j++) {
            float v = p[(size_t)(tc + j) * 512];
            // (1-y) is exactly 0 or 1, so this matches the reference bitwise
            // given identical xw.
            hs = fmaxf(v + 0.8f * hs * (1.0f - y), 0.0f);
            y  = (hs + bb > 0.0f) ? 1.0f : 0.0f;
            buf[threadIdx.x][j] = y;
        }
        __syncthreads();
        const int r = threadIdx.x >> 5;   // 0..3
        const int c = threadIdx.x & 31;   // 0..31
        #pragma unroll
        for (int rr = 0; rr < 128; rr += 4)
            po[(size_t)(rr + r) * 512 + tc + c] = buf[rr + r][c];
        __syncthreads();
    }
}

extern "C" void kernel_launch(void* const* d_in, const int* in_sizes, int n_in,
                              void* d_out, int out_size)
{
    const float* x = (const float*)d_in[0];   // (B, I, T) = (128, 512, 512)
    const float* W = (const float*)d_in[1];   // (I, H)    = (512, 512)
    const float* b = (const float*)d_in[2];   // (1, H)    = (512,)
    float* out = (float*)d_out;               // (B, H, T) float32

    gemm_kernel<<<dim3(4, 512), 256>>>(x, W);
    recur_kernel<<<512, 128>>>(b, out);
}